// round 6
// baseline (speedup 1.0000x reference)
#include <cuda_runtime.h>
#include <cstdint>

// Conv4D with separable rank-1 kernel (K ⊗ K), VALID padding.
// input  : (8192, 8, 8, 8, 8) fp32 -> output (8192, 6, 6, 6, 6) fp32
//
// Persistent CTAs (1024 x 8 batches) with cp.async double-buffered staging:
//   prefetch batch i+1 (gmem -> smem, LDGSTS 4B, coalesced, 65-pad) while
//   computing batch i (pass1 over (d3,d4), pass2 over (d1,d2)).
// All LDS/STS bank-conflict-free: input planes padded to 65 (== 1 mod 32),
// T planes padded to 37 (== 5 mod 32, odd).

#define THREADS 128
#define PER_CTA 8

__device__ __forceinline__ uint32_t smem_u32(const void* p) {
    uint32_t a;
    asm("{ .reg .u64 t; cvta.to.shared.u64 t, %1; cvt.u32.u64 %0, t; }"
        : "=r"(a) : "l"(p));
    return a;
}

__device__ __forceinline__ void cp_async4(uint32_t dst, const float* src) {
    asm volatile("cp.async.ca.shared.global [%0], [%1], 4;\n"
                 :: "r"(dst), "l"(src));
}

__device__ __forceinline__ void cp_commit() {
    asm volatile("cp.async.commit_group;\n");
}

template <int N>
__device__ __forceinline__ void cp_wait() {
    asm volatile("cp.async.wait_group %0;\n" :: "n"(N));
}

__global__ __launch_bounds__(THREADS)
void conv4d_pipe_kernel(const float* __restrict__ in,
                        const float* __restrict__ ker,
                        float* __restrict__ out)
{
    __shared__ float s_in[2][64 * 65];   // 2 x 16,640 B
    __shared__ float s_t[64 * 37];       //     9,472 B

    const int tid = threadIdx.x;
    const int w   = tid & 63;            // word within plane
    const int p0  = tid >> 6;            // 0 or 1

    float k[9];
#pragma unroll
    for (int i = 0; i < 9; i++) k[i] = __ldg(&ker[i]);

    const int  batch0 = blockIdx.x * PER_CTA;

    // addresses for this thread's 32 staging elements (fixed across batches)
    const uint32_t s_base0 = smem_u32(&s_in[0][0]) + (uint32_t)(p0 * 65 + w) * 4u;
    const uint32_t s_base1 = smem_u32(&s_in[1][0]) + (uint32_t)(p0 * 65 + w) * 4u;
    const int      g_off   = p0 * 64 + w;

    // ---- prefetch batch 0 into buffer 0 ----
    {
        const float* gin = in + (size_t)batch0 * 4096;
#pragma unroll
        for (int i = 0; i < 32; i++)
            cp_async4(s_base0 + (uint32_t)(2 * i * 65 * 4), gin + g_off + 2 * i * 64);
        cp_commit();
    }

    for (int it = 0; it < PER_CTA; it++) {
        const int buf = it & 1;

        // ---- prefetch batch it+1 into the other buffer ----
        if (it + 1 < PER_CTA) {
            const float*   gin = in + (size_t)(batch0 + it + 1) * 4096;
            const uint32_t sb  = (buf ? s_base0 : s_base1);
#pragma unroll
            for (int i = 0; i < 32; i++)
                cp_async4(sb + (uint32_t)(2 * i * 65 * 4), gin + g_off + 2 * i * 64);
            cp_commit();
            cp_wait<1>();            // batch `it` complete, next may be in flight
        } else {
            cp_wait<0>();
        }
        __syncthreads();

        // ---- Pass 1: correlate (d3,d4). Thread = (half, ab), rolling 3-row
        // window over 5 rows; lanes along ab -> conflict-free (65 % 32 == 1).
        {
            const int half = tid >> 6;
            const int ab   = tid & 63;
            const float* sp = &s_in[buf][ab * 65 + half * 24];
            float*       tp = &s_t[ab * 37 + half * 18];

            float r[3][8];
#pragma unroll
            for (int c = 0; c < 8; c++) { r[0][c] = sp[c]; r[1][c] = sp[8 + c]; }

#pragma unroll
            for (int e3 = 0; e3 < 3; e3++) {
#pragma unroll
                for (int c = 0; c < 8; c++)
                    r[(e3 + 2) % 3][c] = sp[(e3 + 2) * 8 + c];

                float acc[6];
#pragma unroll
                for (int e4 = 0; e4 < 6; e4++) acc[e4] = 0.0f;
#pragma unroll
                for (int kk = 0; kk < 3; kk++) {
                    const float* row = r[(e3 + kk) % 3];
#pragma unroll
                    for (int ll = 0; ll < 3; ll++) {
                        const float kv = k[kk * 3 + ll];
#pragma unroll
                        for (int e4 = 0; e4 < 6; e4++)
                            acc[e4] = fmaf(row[e4 + ll], kv, acc[e4]);
                    }
                }
#pragma unroll
                for (int e4 = 0; e4 < 6; e4++) tp[e3 * 6 + e4] = acc[e4];
            }
        }
        __syncthreads();   // releases s_in[buf] for the prefetch 2 iters ahead

        // ---- Pass 2: correlate (d1,d2); lanes along e34 -> conflict-free,
        // contiguous coalesced stores.
        float* gout = out + (size_t)(batch0 + it) * 1296;
#pragma unroll
        for (int p = 0; p < 2; p++) {
            const int v = tid + p * THREADS;
            if (v < 216) {
                const int e1  = v / 36;
                const int e34 = v - e1 * 36;

                float t[3][8];
#pragma unroll
                for (int i = 0; i < 3; i++)
#pragma unroll
                    for (int j = 0; j < 8; j++)
                        t[i][j] = s_t[((e1 + i) * 8 + j) * 37 + e34];

                float acc[6];
#pragma unroll
                for (int e2 = 0; e2 < 6; e2++) acc[e2] = 0.0f;
#pragma unroll
                for (int i = 0; i < 3; i++)
#pragma unroll
                    for (int j = 0; j < 3; j++) {
                        const float kv = k[i * 3 + j];
#pragma unroll
                        for (int e2 = 0; e2 < 6; e2++)
                            acc[e2] = fmaf(t[i][e2 + j], kv, acc[e2]);
                    }

#pragma unroll
                for (int e2 = 0; e2 < 6; e2++)
                    gout[e1 * 216 + e2 * 36 + e34] = acc[e2];
            }
        }
        // next iteration's top __syncthreads orders pass2 reads of s_t
        // before pass1 overwrites it
    }
}

extern "C" void kernel_launch(void* const* d_in, const int* in_sizes, int n_in,
                              void* d_out, int out_size)
{
    const float* in  = (const float*)d_in[0];   // (8192,8,8,8,8) fp32
    const float* ker = (const float*)d_in[1];   // (3,3) fp32
    float*       out = (float*)d_out;           // (8192,6,6,6,6) fp32

    const int batches = in_sizes[0] / 4096;     // 8192
    const int n_ctas  = batches / PER_CTA;      // 1024
    conv4d_pipe_kernel<<<n_ctas, THREADS>>>(in, ker, out);
}